// round 9
// baseline (speedup 1.0000x reference)
#include <cuda_runtime.h>

#define NNODE 17
#define TPB   544      // 17 full warps: warp = one node x 32 graphs
#define NG    32       // graphs per block, one per lane

typedef unsigned long long u64;

// packed fp32x2 ops (Blackwell); ptxas never auto-fuses these from C++
__device__ __forceinline__ u64 ffma2(u64 a, u64 b, u64 c) {
    u64 d;
    asm("fma.rn.f32x2 %0, %1, %2, %3;" : "=l"(d) : "l"(a), "l"(b), "l"(c));
    return d;
}
__device__ __forceinline__ u64 add2(u64 a, u64 b) {
    u64 d;
    asm("add.rn.f32x2 %0, %1, %2;" : "=l"(d) : "l"(a), "l"(b));
    return d;
}
__device__ __forceinline__ u64 mul2(u64 a, u64 b) {
    u64 d;
    asm("mul.rn.f32x2 %0, %1, %2;" : "=l"(d) : "l"(a), "l"(b));
    return d;
}
__device__ __forceinline__ u64 bcast2(float v) {
    u64 d; unsigned r = __float_as_uint(v);
    asm("mov.b64 %0, {%1, %1};" : "=l"(d) : "r"(r));
    return d;
}
__device__ __forceinline__ u64 pack2(float x, float y) {
    u64 d;
    asm("mov.b64 %0, {%1, %2};" : "=l"(d) : "r"(__float_as_uint(x)), "r"(__float_as_uint(y)));
    return d;
}
__device__ __forceinline__ void unpk(u64 d, float& x, float& y) {
    unsigned a, b;
    asm("mov.b64 {%0, %1}, %2;" : "=r"(a), "=r"(b) : "l"(d));
    x = __uint_as_float(a); y = __uint_as_float(b);
}

// ---- dynamic shared layout (float offsets) ----
#define FCS   0        // fc_w: 32 rows x 160 (136 used; warp's column-block in one 128B line)
#define W1S   5120     // 8x16
#define B1S   5248     // 16
#define W2S   5264     // 16x32
#define B2S   5776     // 32
#define W3S   5808     // 32x32
#define B3S   6832     // 32
#define ZS    6864     // 32 graphs x 36
#define ARENA 8016     // 544 rows x 36 floats (exchange + out staging)
#define SHFLOATS 27600 // 110400 bytes per block (x2 blocks <= 228KB/SM)

extern __shared__ float sh[];

__global__ void __launch_bounds__(TPB, 2)
gnn_fused(const float* __restrict__ z,
          const float* __restrict__ fc_w, const float* __restrict__ fc_b,
          const float* __restrict__ w1,   const float* __restrict__ b1,
          const float* __restrict__ w2,   const float* __restrict__ b2,
          const float* __restrict__ w3,   const float* __restrict__ b3,
          float* __restrict__ out)
{
    const int tid = threadIdx.x;

    // ---------------- stage weights + z into shared (strided loops) ----------
    for (int i = tid; i < 4352; i += TPB) {            // fc_w rows padded 136->160
        int k = i / 136, c = i - k * 136;
        sh[FCS + k * 160 + c] = fc_w[i];
    }
    for (int i = tid; i < 128;  i += TPB) sh[W1S + i] = w1[i];
    for (int i = tid; i < 512;  i += TPB) sh[W2S + i] = w2[i];
    for (int i = tid; i < 1024; i += TPB) sh[W3S + i] = w3[i];
    if (tid < 16)                         sh[B1S + tid] = b1[tid];
    else if (tid >= 32 && tid < 64)       sh[B2S + tid - 32] = b2[tid - 32];
    else if (tid >= 64 && tid < 96)       sh[B3S + tid - 64] = b3[tid - 64];
    {
        const float* zblk = z + (size_t)blockIdx.x * (NG * 32);
        for (int i = tid; i < NG * 32; i += TPB)
            sh[ZS + (i >> 5) * 36 + (i & 31)] = zblk[i];
    }
    __syncthreads();

    // warp = node n (uniform per warp), lane = graph g
    const int n  = tid >> 5;
    const int g  = tid & 31;
    const int rp = (n == NNODE - 1) ? g       : tid + 32;  // row of node (n+1)%17
    const int rm = (n == 0)         ? 512 + g : tid - 32;  // row of node (n-1)%17
    const u64 third2 = bcast2(1.0f / 3.0f);

    // ================= FC: x0 = z @ fc_w[:, 8n:8n+8] + fc_b ==================
    u64 x0p[4];
    {
        float zr[32];
        const float4* zp = (const float4*)(sh + ZS + g * 36);
        #pragma unroll
        for (int i = 0; i < 8; i++) {
            float4 v = zp[i];
            zr[4*i] = v.x; zr[4*i+1] = v.y; zr[4*i+2] = v.z; zr[4*i+3] = v.w;
        }
        const u64* fb = (const u64*)fc_b + n * 4;      // warp-uniform LDG
        #pragma unroll
        for (int i = 0; i < 4; i++) x0p[i] = __ldg(fb + i);
        #pragma unroll
        for (int k = 0; k < 32; k++) {
            const ulonglong2* w = (const ulonglong2*)(sh + FCS + k * 160 + n * 8);
            ulonglong2 wa = w[0], wb = w[1];
            u64 zz = bcast2(zr[k]);
            x0p[0] = ffma2(zz, wa.x, x0p[0]);
            x0p[1] = ffma2(zz, wa.y, x0p[1]);
            x0p[2] = ffma2(zz, wb.x, x0p[2]);
            x0p[3] = ffma2(zz, wb.y, x0p[3]);
        }
    }
    {
        ulonglong2* row = (ulonglong2*)(sh + ARENA + tid * 36);
        row[0] = make_ulonglong2(x0p[0], x0p[1]);
        row[1] = make_ulonglong2(x0p[2], x0p[3]);
    }
    __syncthreads();
    float a0[8];
    {
        const ulonglong2* p = (const ulonglong2*)(sh + ARENA + rp * 36);
        const ulonglong2* m = (const ulonglong2*)(sh + ARENA + rm * 36);
        #pragma unroll
        for (int q = 0; q < 2; q++) {
            ulonglong2 pv = p[q], mv = m[q];
            u64 t0 = mul2(add2(add2(x0p[2*q],   pv.x), mv.x), third2);
            u64 t1 = mul2(add2(add2(x0p[2*q+1], pv.y), mv.y), third2);
            unpk(t0, a0[4*q+0], a0[4*q+1]);
            unpk(t1, a0[4*q+2], a0[4*q+3]);
        }
    }
    __syncthreads();

    // ================= conv1: x1 = relu(a0 @ w1 + b1), 16 out =================
    u64 x1p[8];
    {
        u64 acc[8];
        const u64* bb = (const u64*)(sh + B1S);
        #pragma unroll
        for (int j = 0; j < 8; j++) acc[j] = bb[j];
        #pragma unroll
        for (int k = 0; k < 8; k++) {
            u64 av = bcast2(a0[k]);
            const ulonglong2* w = (const ulonglong2*)(sh + W1S + k * 16);
            #pragma unroll
            for (int q = 0; q < 4; q++) {
                ulonglong2 t = w[q];
                acc[2*q]   = ffma2(av, t.x, acc[2*q]);
                acc[2*q+1] = ffma2(av, t.y, acc[2*q+1]);
            }
        }
        #pragma unroll
        for (int j = 0; j < 8; j++) {
            float x, y; unpk(acc[j], x, y);
            x1p[j] = pack2(fmaxf(x, 0.0f), fmaxf(y, 0.0f));
        }
    }
    {
        ulonglong2* row = (ulonglong2*)(sh + ARENA + tid * 36);
        #pragma unroll
        for (int q = 0; q < 4; q++)
            row[q] = make_ulonglong2(x1p[2*q], x1p[2*q+1]);
    }
    __syncthreads();
    float a1[16];
    {
        const ulonglong2* p = (const ulonglong2*)(sh + ARENA + rp * 36);
        const ulonglong2* m = (const ulonglong2*)(sh + ARENA + rm * 36);
        #pragma unroll
        for (int q = 0; q < 4; q++) {
            ulonglong2 pv = p[q], mv = m[q];
            u64 t0 = mul2(add2(add2(x1p[2*q],   pv.x), mv.x), third2);
            u64 t1 = mul2(add2(add2(x1p[2*q+1], pv.y), mv.y), third2);
            unpk(t0, a1[4*q+0], a1[4*q+1]);
            unpk(t1, a1[4*q+2], a1[4*q+3]);
        }
    }
    __syncthreads();

    // ====== conv2: x2 = relu(a1 @ w2 + b2), 32 out, j-halves, to arena ========
    #pragma unroll
    for (int h = 0; h < 2; h++) {
        u64 acc[8];
        const u64* bb = (const u64*)(sh + B2S + h * 16);
        #pragma unroll
        for (int j = 0; j < 8; j++) acc[j] = bb[j];
        #pragma unroll
        for (int k = 0; k < 16; k++) {
            u64 av = bcast2(a1[k]);
            const ulonglong2* w = (const ulonglong2*)(sh + W2S + k * 32 + h * 16);
            #pragma unroll
            for (int q = 0; q < 4; q++) {
                ulonglong2 t = w[q];
                acc[2*q]   = ffma2(av, t.x, acc[2*q]);
                acc[2*q+1] = ffma2(av, t.y, acc[2*q+1]);
            }
        }
        u64 xp[8];
        #pragma unroll
        for (int j = 0; j < 8; j++) {
            float x, y; unpk(acc[j], x, y);
            xp[j] = pack2(fmaxf(x, 0.0f), fmaxf(y, 0.0f));
        }
        ulonglong2* row = (ulonglong2*)(sh + ARENA + tid * 36 + h * 16);
        #pragma unroll
        for (int q = 0; q < 4; q++)
            row[q] = make_ulonglong2(xp[2*q], xp[2*q+1]);
    }
    __syncthreads();
    float a2[32];
    {
        const ulonglong2* o = (const ulonglong2*)(sh + ARENA + tid * 36);
        const ulonglong2* p = (const ulonglong2*)(sh + ARENA + rp * 36);
        const ulonglong2* m = (const ulonglong2*)(sh + ARENA + rm * 36);
        #pragma unroll
        for (int q = 0; q < 8; q++) {
            ulonglong2 ov = o[q], pv = p[q], mv = m[q];
            u64 t0 = mul2(add2(add2(ov.x, pv.x), mv.x), third2);
            u64 t1 = mul2(add2(add2(ov.y, pv.y), mv.y), third2);
            unpk(t0, a2[4*q+0], a2[4*q+1]);
            unpk(t1, a2[4*q+2], a2[4*q+3]);
        }
    }
    __syncthreads();   // arena reused below for out staging

    // ====== conv3: out = a2 @ w3 + b3, j-halves, stage to arena ===============
    #pragma unroll
    for (int h = 0; h < 2; h++) {
        u64 acc[8];
        const u64* bb = (const u64*)(sh + B3S + h * 16);
        #pragma unroll
        for (int j = 0; j < 8; j++) acc[j] = bb[j];
        #pragma unroll
        for (int k = 0; k < 32; k++) {
            u64 av = bcast2(a2[k]);
            const ulonglong2* w = (const ulonglong2*)(sh + W3S + k * 32 + h * 16);
            #pragma unroll
            for (int q = 0; q < 4; q++) {
                ulonglong2 t = w[q];
                acc[2*q]   = ffma2(av, t.x, acc[2*q]);
                acc[2*q+1] = ffma2(av, t.y, acc[2*q+1]);
            }
        }
        // stage in out layout: row = g*17 + n, columns h*16 .. h*16+15
        ulonglong2* row = (ulonglong2*)(sh + ARENA + (g * 17 + n) * 36 + h * 16);
        #pragma unroll
        for (int q = 0; q < 4; q++)
            row[q] = make_ulonglong2(acc[2*q], acc[2*q+1]);
    }
    __syncthreads();

    // coalesced global write: 32*17*32 floats contiguous per block
    float4* og = (float4*)(out + (size_t)blockIdx.x * (NG * NNODE * 32));
    #pragma unroll
    for (int it = 0; it < 8; it++) {
        int q = tid + it * TPB;                 // 0 .. 4351
        int row = q >> 3, c = q & 7;
        og[q] = *(const float4*)(sh + ARENA + row * 36 + c * 4);
    }
}

extern "C" void kernel_launch(void* const* d_in, const int* in_sizes, int n_in,
                              void* d_out, int out_size) {
    const float* z    = (const float*)d_in[0];
    // d_in[1] = edge_index: fixed ring, degree==3 everywhere -> norm==1/3; unused
    const float* fc_w = (const float*)d_in[2];
    const float* fc_b = (const float*)d_in[3];
    const float* w1   = (const float*)d_in[4];
    const float* b1   = (const float*)d_in[5];
    const float* w2   = (const float*)d_in[6];
    const float* b2   = (const float*)d_in[7];
    const float* w3   = (const float*)d_in[8];
    const float* b3   = (const float*)d_in[9];

    cudaFuncSetAttribute(gnn_fused, cudaFuncAttributeMaxDynamicSharedMemorySize,
                         SHFLOATS * 4);

    const int B    = in_sizes[0] / 32;      // 65536 graphs
    const int grid = B / NG;                // 2048 blocks
    gnn_fused<<<grid, TPB, SHFLOATS * 4>>>(z, fc_w, fc_b, w1, b1, w2, b2, w3, b3,
                                           (float*)d_out);
}

// round 10
// speedup vs baseline: 1.0800x; 1.0800x over previous
#include <cuda_runtime.h>

#define NNODE 17
#define TPB   272      // 17 nodes x 16 graph-lanes
#define NG    32       // graphs per block: 2 graph-sets per thread (s = 0,1)

typedef unsigned long long u64;

// packed fp32x2 ops (Blackwell); ptxas never auto-fuses these from C++
__device__ __forceinline__ u64 ffma2(u64 a, u64 b, u64 c) {
    u64 d;
    asm("fma.rn.f32x2 %0, %1, %2, %3;" : "=l"(d) : "l"(a), "l"(b), "l"(c));
    return d;
}
__device__ __forceinline__ u64 add2(u64 a, u64 b) {
    u64 d;
    asm("add.rn.f32x2 %0, %1, %2;" : "=l"(d) : "l"(a), "l"(b));
    return d;
}
__device__ __forceinline__ u64 mul2(u64 a, u64 b) {
    u64 d;
    asm("mul.rn.f32x2 %0, %1, %2;" : "=l"(d) : "l"(a), "l"(b));
    return d;
}
__device__ __forceinline__ u64 bcast2(float v) {
    u64 d; unsigned r = __float_as_uint(v);
    asm("mov.b64 %0, {%1, %1};" : "=l"(d) : "r"(r));
    return d;
}
__device__ __forceinline__ u64 pack2(float x, float y) {
    u64 d;
    asm("mov.b64 %0, {%1, %2};" : "=l"(d) : "r"(__float_as_uint(x)), "r"(__float_as_uint(y)));
    return d;
}
__device__ __forceinline__ void unpk(u64 d, float& x, float& y) {
    unsigned a, b;
    asm("mov.b64 {%0, %1}, %2;" : "=r"(a), "=r"(b) : "l"(d));
    x = __uint_as_float(a); y = __uint_as_float(b);
}

// ---- dynamic shared layout (float offsets) ----
#define FCS   0        // fc_w: 32 rows x 160 (136 used; warp's n-pair in one 128B line)
#define W1S   5120     // 8x16
#define B1S   5248     // 16
#define W2S   5264     // 16x32
#define B2S   5776     // 32
#define W3S   5808     // 32x32
#define B3S   6832     // 32
#define ZS    6864     // 32 graphs x 36
#define ARENA 8016     // 544 rows x 36 floats (exchange + out staging)
#define SHFLOATS 27600 // 110400 bytes per block (x2 blocks <= 228KB/SM)

extern __shared__ float sh[];

__global__ void __launch_bounds__(TPB, 2)
gnn_fused(const float* __restrict__ z,
          const float* __restrict__ fc_w, const float* __restrict__ fc_b,
          const float* __restrict__ w1,   const float* __restrict__ b1,
          const float* __restrict__ w2,   const float* __restrict__ b2,
          const float* __restrict__ w3,   const float* __restrict__ b3,
          float* __restrict__ out)
{
    const int tid = threadIdx.x;

    // ---------------- stage weights + z into shared ----------------
    for (int i = tid; i < 4352; i += TPB) {            // fc_w rows padded 136->160
        int k = i / 136, c = i - k * 136;
        sh[FCS + k * 160 + c] = fc_w[i];
    }
    for (int i = tid; i < 128;  i += TPB) sh[W1S + i] = w1[i];
    for (int i = tid; i < 512;  i += TPB) sh[W2S + i] = w2[i];
    for (int i = tid; i < 1024; i += TPB) sh[W3S + i] = w3[i];
    if (tid < 16)                         sh[B1S + tid] = b1[tid];
    else if (tid >= 32 && tid < 64)       sh[B2S + tid - 32] = b2[tid - 32];
    else if (tid >= 64 && tid < 96)       sh[B3S + tid - 64] = b3[tid - 64];
    {
        const float* zblk = z + (size_t)blockIdx.x * (NG * 32);
        for (int i = tid; i < NG * 32; i += TPB)
            sh[ZS + (i >> 5) * 36 + (i & 31)] = zblk[i];
    }
    __syncthreads();

    // thread = node n, graphs g and g+16; warp holds 2 nodes x 16 lanes
    const int n  = tid >> 4;
    const int g  = tid & 15;
    const int rp = (n == NNODE - 1) ? g       : tid + 16;  // row of node (n+1)%17
    const int rm = (n == 0)         ? 256 + g : tid - 16;  // row of node (n-1)%17
    const u64 third2 = bcast2(1.0f / 3.0f);

    // ================= FC: x0 = z @ fc_w[:, 8n:8n+8] + fc_b ==================
    u64 x0p[2][4];                                      // packed x0 (8 floats = 4 u64)
    {
        float zr[2][32];
        #pragma unroll
        for (int s = 0; s < 2; s++) {
            const float4* zp = (const float4*)(sh + ZS + (g + 16 * s) * 36);
            #pragma unroll
            for (int i = 0; i < 8; i++) {
                float4 v = zp[i];
                zr[s][4*i] = v.x; zr[s][4*i+1] = v.y; zr[s][4*i+2] = v.z; zr[s][4*i+3] = v.w;
            }
        }
        {
            const u64* fb = (const u64*)fc_b + n * 4;
            #pragma unroll
            for (int i = 0; i < 4; i++) { u64 b = __ldg(fb + i); x0p[0][i] = b; x0p[1][i] = b; }
        }
        #pragma unroll
        for (int k = 0; k < 32; k++) {
            const ulonglong2* w = (const ulonglong2*)(sh + FCS + k * 160 + n * 8);
            ulonglong2 wa = w[0], wb = w[1];
            #pragma unroll
            for (int s = 0; s < 2; s++) {
                u64 zz = bcast2(zr[s][k]);
                x0p[s][0] = ffma2(zz, wa.x, x0p[s][0]);
                x0p[s][1] = ffma2(zz, wa.y, x0p[s][1]);
                x0p[s][2] = ffma2(zz, wb.x, x0p[s][2]);
                x0p[s][3] = ffma2(zz, wb.y, x0p[s][3]);
            }
        }
    }
    #pragma unroll
    for (int s = 0; s < 2; s++) {
        ulonglong2* row = (ulonglong2*)(sh + ARENA + (s * 272 + tid) * 36);
        row[0] = make_ulonglong2(x0p[s][0], x0p[s][1]);
        row[1] = make_ulonglong2(x0p[s][2], x0p[s][3]);
    }
    __syncthreads();
    float a0[2][8];
    #pragma unroll
    for (int s = 0; s < 2; s++) {
        const ulonglong2* p = (const ulonglong2*)(sh + ARENA + (s * 272 + rp) * 36);
        const ulonglong2* m = (const ulonglong2*)(sh + ARENA + (s * 272 + rm) * 36);
        #pragma unroll
        for (int q = 0; q < 2; q++) {
            ulonglong2 pv = p[q], mv = m[q];
            u64 t0 = mul2(add2(add2(x0p[s][2*q],   pv.x), mv.x), third2);
            u64 t1 = mul2(add2(add2(x0p[s][2*q+1], pv.y), mv.y), third2);
            unpk(t0, a0[s][4*q+0], a0[s][4*q+1]);
            unpk(t1, a0[s][4*q+2], a0[s][4*q+3]);
        }
    }
    __syncthreads();

    // ================= conv1: x1 = relu(a0 @ w1 + b1), 16 out =================
    u64 x1p[2][8];
    {
        u64 acc[2][8];
        const u64* bb = (const u64*)(sh + B1S);
        #pragma unroll
        for (int j = 0; j < 8; j++) { u64 b = bb[j]; acc[0][j] = b; acc[1][j] = b; }
        #pragma unroll
        for (int k = 0; k < 8; k++) {
            const ulonglong2* w = (const ulonglong2*)(sh + W1S + k * 16);
            #pragma unroll
            for (int q = 0; q < 4; q++) {
                ulonglong2 t = w[q];
                #pragma unroll
                for (int s = 0; s < 2; s++) {
                    u64 av = bcast2(a0[s][k]);
                    acc[s][2*q]   = ffma2(av, t.x, acc[s][2*q]);
                    acc[s][2*q+1] = ffma2(av, t.y, acc[s][2*q+1]);
                }
            }
        }
        #pragma unroll
        for (int s = 0; s < 2; s++)
            #pragma unroll
            for (int j = 0; j < 8; j++) {
                float x, y; unpk(acc[s][j], x, y);
                x1p[s][j] = pack2(fmaxf(x, 0.0f), fmaxf(y, 0.0f));
            }
    }
    #pragma unroll
    for (int s = 0; s < 2; s++) {
        ulonglong2* row = (ulonglong2*)(sh + ARENA + (s * 272 + tid) * 36);
        #pragma unroll
        for (int q = 0; q < 4; q++)
            row[q] = make_ulonglong2(x1p[s][2*q], x1p[s][2*q+1]);
    }
    __syncthreads();
    float a1[2][16];
    #pragma unroll
    for (int s = 0; s < 2; s++) {
        const ulonglong2* p = (const ulonglong2*)(sh + ARENA + (s * 272 + rp) * 36);
        const ulonglong2* m = (const ulonglong2*)(sh + ARENA + (s * 272 + rm) * 36);
        #pragma unroll
        for (int q = 0; q < 4; q++) {
            ulonglong2 pv = p[q], mv = m[q];
            u64 t0 = mul2(add2(add2(x1p[s][2*q],   pv.x), mv.x), third2);
            u64 t1 = mul2(add2(add2(x1p[s][2*q+1], pv.y), mv.y), third2);
            unpk(t0, a1[s][4*q+0], a1[s][4*q+1]);
            unpk(t1, a1[s][4*q+2], a1[s][4*q+3]);
        }
    }
    __syncthreads();

    // ====== conv2: x2 = relu(a1 @ w2 + b2), 32 out, j-halves ==================
    // x2 kept PACKED in registers across the barrier (kills the self re-read)
    u64 x2p[2][16];
    #pragma unroll
    for (int h = 0; h < 2; h++) {
        u64 acc[2][8];
        const u64* bb = (const u64*)(sh + B2S + h * 16);
        #pragma unroll
        for (int j = 0; j < 8; j++) { u64 b = bb[j]; acc[0][j] = b; acc[1][j] = b; }
        #pragma unroll
        for (int k = 0; k < 16; k++) {
            const ulonglong2* w = (const ulonglong2*)(sh + W2S + k * 32 + h * 16);
            #pragma unroll
            for (int q = 0; q < 4; q++) {
                ulonglong2 t = w[q];
                #pragma unroll
                for (int s = 0; s < 2; s++) {
                    u64 av = bcast2(a1[s][k]);
                    acc[s][2*q]   = ffma2(av, t.x, acc[s][2*q]);
                    acc[s][2*q+1] = ffma2(av, t.y, acc[s][2*q+1]);
                }
            }
        }
        #pragma unroll
        for (int s = 0; s < 2; s++) {
            #pragma unroll
            for (int j = 0; j < 8; j++) {
                float x, y; unpk(acc[s][j], x, y);
                x2p[s][h * 8 + j] = pack2(fmaxf(x, 0.0f), fmaxf(y, 0.0f));
            }
            ulonglong2* row = (ulonglong2*)(sh + ARENA + (s * 272 + tid) * 36 + h * 16);
            #pragma unroll
            for (int q = 0; q < 4; q++)
                row[q] = make_ulonglong2(x2p[s][h*8 + 2*q], x2p[s][h*8 + 2*q + 1]);
        }
    }
    __syncthreads();
    float a2[2][32];
    #pragma unroll
    for (int s = 0; s < 2; s++) {
        const ulonglong2* p = (const ulonglong2*)(sh + ARENA + (s * 272 + rp) * 36);
        const ulonglong2* m = (const ulonglong2*)(sh + ARENA + (s * 272 + rm) * 36);
        #pragma unroll
        for (int q = 0; q < 8; q++) {
            ulonglong2 pv = p[q], mv = m[q];
            u64 t0 = mul2(add2(add2(x2p[s][2*q],   pv.x), mv.x), third2);
            u64 t1 = mul2(add2(add2(x2p[s][2*q+1], pv.y), mv.y), third2);
            unpk(t0, a2[s][4*q+0], a2[s][4*q+1]);
            unpk(t1, a2[s][4*q+2], a2[s][4*q+3]);
        }
    }
    __syncthreads();   // arena reused below for out staging

    // ====== conv3: out = a2 @ w3 + b3, j-halves, stage to arena ===============
    #pragma unroll
    for (int h = 0; h < 2; h++) {
        u64 acc[2][8];
        const u64* bb = (const u64*)(sh + B3S + h * 16);
        #pragma unroll
        for (int j = 0; j < 8; j++) { u64 b = bb[j]; acc[0][j] = b; acc[1][j] = b; }
        #pragma unroll
        for (int k = 0; k < 32; k++) {
            const ulonglong2* w = (const ulonglong2*)(sh + W3S + k * 32 + h * 16);
            #pragma unroll
            for (int q = 0; q < 4; q++) {
                ulonglong2 t = w[q];
                #pragma unroll
                for (int s = 0; s < 2; s++) {
                    u64 av = bcast2(a2[s][k]);
                    acc[s][2*q]   = ffma2(av, t.x, acc[s][2*q]);
                    acc[s][2*q+1] = ffma2(av, t.y, acc[s][2*q+1]);
                }
            }
        }
        // stage in out layout: row = (g + 16s)*17 + n, columns h*16 .. h*16+15
        #pragma unroll
        for (int s = 0; s < 2; s++) {
            ulonglong2* row = (ulonglong2*)(sh + ARENA + ((g + 16 * s) * 17 + n) * 36 + h * 16);
            #pragma unroll
            for (int q = 0; q < 4; q++)
                row[q] = make_ulonglong2(acc[s][2*q], acc[s][2*q+1]);
        }
    }
    __syncthreads();

    // coalesced global write: 32*17*32 floats contiguous per block
    float4* og = (float4*)(out + (size_t)blockIdx.x * (NG * NNODE * 32));
    #pragma unroll
    for (int it = 0; it < 16; it++) {
        int q = tid + it * TPB;                 // 0 .. 4351
        int row = q >> 3, c = q & 7;
        og[q] = *(const float4*)(sh + ARENA + row * 36 + c * 4);
    }
}

extern "C" void kernel_launch(void* const* d_in, const int* in_sizes, int n_in,
                              void* d_out, int out_size) {
    const float* z    = (const float*)d_in[0];
    // d_in[1] = edge_index: fixed ring, degree==3 everywhere -> norm==1/3; unused
    const float* fc_w = (const float*)d_in[2];
    const float* fc_b = (const float*)d_in[3];
    const float* w1   = (const float*)d_in[4];
    const float* b1   = (const float*)d_in[5];
    const float* w2   = (const float*)d_in[6];
    const float* b2   = (const float*)d_in[7];
    const float* w3   = (const float*)d_in[8];
    const float* b3   = (const float*)d_in[9];

    cudaFuncSetAttribute(gnn_fused, cudaFuncAttributeMaxDynamicSharedMemorySize,
                         SHFLOATS * 4);

    const int B    = in_sizes[0] / 32;      // 65536 graphs
    const int grid = B / NG;                // 2048 blocks
    gnn_fused<<<grid, TPB, SHFLOATS * 4>>>(z, fc_w, fc_b, w1, b1, w2, b2, w3, b3,
                                           (float*)d_out);
}